// round 1
// baseline (speedup 1.0000x reference)
#include <cuda_runtime.h>

// MovingNCA restructured:
//  - 96-channel state replaced by 9 planes P_ij(x,y) = sum_c state[x,y,c]*comms_w[i,j,c]
//  - comms(n,m) = sum_ij P_ij(n+i, m+j)  (9-point gather across 9 planes)
//  - per-cell update: s_c = sigmoid(a*u_c + b*v_c + ob_c); P_ij(n+1,m+1) += sum_c w_ij,c * s_c
//  - class channels (64..95) accumulate directly into d_out
//  - perc positions carried as ushort2
// 50 step launches (ping-pong planes) provide the inter-iteration barrier.

#define N_NEO 510
#define G     512
#define G2    (G * G)
#define NCELLS (N_NEO * N_NEO)
#define NCA_THRESH 0.0007f

__device__ float   g_h[2][9][G2];     // ping-pong comms planes
__device__ ushort2 g_perc[NCELLS];    // perception positions

__global__ void nca_init(float* __restrict__ out) {
    long stride = (long)gridDim.x * blockDim.x;
    long tid = (long)blockIdx.x * blockDim.x + threadIdx.x;
    float* h = &g_h[0][0][0];
    for (long i = tid; i < 2L * 9 * G2; i += stride) h[i] = 0.0f;
    for (long i = tid; i < (long)NCELLS * 32; i += stride) out[i] = 0.0f;
    for (long i = tid; i < NCELLS; i += stride)
        g_perc[i] = make_ushort2((unsigned short)(i / N_NEO),
                                 (unsigned short)(i % N_NEO));
}

__global__ __launch_bounds__(256) void nca_step(
    const float* __restrict__ img,
    const float* __restrict__ comms_w,
    const float* __restrict__ comms_b,
    const float* __restrict__ perc_w,
    const float* __restrict__ perc_b,
    const float* __restrict__ out_w,
    const float* __restrict__ out_b,
    float* __restrict__ out,
    int parity)
{
    __shared__ float scw[9 * 96];        // comms_w, layout [ij][c] (same as input)
    __shared__ float su[98], sv[98], sob[98], spw[9];
    __shared__ float sbias[2];           // [0]=perc_b, [1]=comms_b

    int t = threadIdx.y * 32 + threadIdx.x;
    for (int i = t; i < 864; i += 256) scw[i] = comms_w[i];
    if (t < 98) { su[t] = out_w[t]; sv[t] = out_w[98 + t]; sob[t] = out_b[t]; }
    else if (t >= 128 && t < 137) spw[t - 128] = perc_w[t - 128];
    else if (t == 137) sbias[0] = perc_b[0];
    else if (t == 138) sbias[1] = comms_b[0];
    __syncthreads();

    int m = blockIdx.x * 32 + threadIdx.x;
    int n = blockIdx.y * 8 + threadIdx.y;
    if (m >= N_NEO || n >= N_NEO) return;

    const float* __restrict__ hOld = &g_h[parity][0][0];
    float* __restrict__ hNew = &g_h[parity ^ 1][0][0];

    // ---- comms: a = comms_b + sum_ij P_ij(n+i, m+j)
    float a = sbias[1];
#pragma unroll
    for (int q = 0; q < 9; q++) {
        int i = q / 3, j = q % 3;
        a += hOld[q * G2 + (n + i) * G + (m + j)];
    }

    // ---- percep: b = perc_b + sum_ij img[px+i, py+j] * pw[i,j]
    int cell = n * N_NEO + m;
    ushort2 p = g_perc[cell];
    float b = sbias[0];
#pragma unroll
    for (int q = 0; q < 9; q++) {
        int i = q / 3, j = q % 3;
        b = fmaf(img[(p.x + i) * G + (p.y + j)], spw[q], b);
    }

    float acc[9] = {0.f, 0.f, 0.f, 0.f, 0.f, 0.f, 0.f, 0.f, 0.f};

    // hidden channels 0..63
#pragma unroll 8
    for (int c = 0; c < 64; c++) {
        float x = fmaf(a, su[c], fmaf(b, sv[c], sob[c]));
        float s = __fdividef(1.0f, 1.0f + __expf(-x));
#pragma unroll
        for (int q = 0; q < 9; q++) acc[q] = fmaf(scw[q * 96 + c], s, acc[q]);
    }

    // class channels 64..95 (also accumulated into out)
    float so[32];
#pragma unroll
    for (int k = 0; k < 32; k++) {
        int c = 64 + k;
        float x = fmaf(a, su[c], fmaf(b, sv[c], sob[c]));
        float s = __fdividef(1.0f, 1.0f + __expf(-x));
        so[k] = s;
#pragma unroll
        for (int q = 0; q < 9; q++) acc[q] = fmaf(scw[q * 96 + c], s, acc[q]);
    }

    // accumulate class outputs (vectorized read-modify-write, 128B per cell)
    float* op = out + (size_t)cell * 32;
#pragma unroll
    for (int k = 0; k < 32; k += 4) {
        float4 v = *reinterpret_cast<float4*>(op + k);
        v.x += so[k]; v.y += so[k + 1]; v.z += so[k + 2]; v.w += so[k + 3];
        *reinterpret_cast<float4*>(op + k) = v;
    }

    // write updated planes at this cell's grid position (n+1, m+1)
    int hc = (n + 1) * G + (m + 1);
#pragma unroll
    for (int q = 0; q < 9; q++)
        hNew[q * G2 + hc] = hOld[q * G2 + hc] + acc[q];

    // action channels 96, 97 -> perc update
    float x0 = fmaf(a, su[96], fmaf(b, sv[96], sob[96]));
    float s0 = __fdividef(1.0f, 1.0f + __expf(-x0));
    float x1 = fmaf(a, su[97], fmaf(b, sv[97], sob[97]));
    float s1 = __fdividef(1.0f, 1.0f + __expf(-x1));
    int dx = (s0 > NCA_THRESH) ? 1 : ((s0 < -NCA_THRESH) ? -1 : 0);
    int dy = (s1 > NCA_THRESH) ? 1 : ((s1 < -NCA_THRESH) ? -1 : 0);
    int px = min(max((int)p.x + dx, 0), N_NEO - 1);
    int py = min(max((int)p.y + dy, 0), N_NEO - 1);
    g_perc[cell] = make_ushort2((unsigned short)px, (unsigned short)py);
}

extern "C" void kernel_launch(void* const* d_in, const int* in_sizes, int n_in,
                              void* d_out, int out_size) {
    const float* img     = (const float*)d_in[0];
    const float* comms_w = (const float*)d_in[1];
    const float* comms_b = (const float*)d_in[2];
    const float* perc_w  = (const float*)d_in[3];
    const float* perc_b  = (const float*)d_in[4];
    const float* out_w   = (const float*)d_in[5];
    const float* out_b   = (const float*)d_in[6];
    float* out = (float*)d_out;

    nca_init<<<1024, 256>>>(out);

    dim3 bs(32, 8);
    dim3 gs((N_NEO + 31) / 32, (N_NEO + 7) / 8);
    for (int t = 0; t < 50; t++)
        nca_step<<<gs, bs>>>(img, comms_w, comms_b, perc_w, perc_b,
                             out_w, out_b, out, t & 1);
}

// round 2
// speedup vs baseline: 1.6680x; 1.6680x over previous
#include <cuda_runtime.h>

// MovingNCA, plane-reduced formulation:
//  state(96ch) replaced by 9 planes P_ij = <state, comms_w[i,j,:]>.
//  comms a = b_c + sum_ij P_ij(n+i,m+j); percep b = 3x3 img gather at perc pos.
//  s_c = sigmoid(a*u_c + b*v_c + ob_c); planes += W^T s; class ch -> d_out.
// R2: 4 cells/thread (m,m+32,m+64,m+96) + float4 LDS to fix issue-bound profile.

#define N_NEO 510
#define G     512
#define G2    (G * G)
#define NCELLS (N_NEO * N_NEO)
#define NCA_THRESH 0.0007f

__device__ float   g_h[2][9][G2];     // ping-pong comms planes
__device__ ushort2 g_perc[NCELLS];    // perception positions

__global__ void nca_init(float* __restrict__ out) {
    long stride = (long)gridDim.x * blockDim.x;
    long tid = (long)blockIdx.x * blockDim.x + threadIdx.x;
    float* h = &g_h[0][0][0];
    for (long i = tid; i < 2L * 9 * G2; i += stride) h[i] = 0.0f;
    for (long i = tid; i < (long)NCELLS * 32; i += stride) out[i] = 0.0f;
    for (long i = tid; i < NCELLS; i += stride)
        g_perc[i] = make_ushort2((unsigned short)(i / N_NEO),
                                 (unsigned short)(i % N_NEO));
}

__device__ __forceinline__ float sigmoidf(float x) {
    float e;
    asm("ex2.approx.f32 %0, %1;" : "=f"(e) : "f"(-1.442695041f * x));
    float r;
    asm("rcp.approx.f32 %0, %1;" : "=f"(r) : "f"(1.0f + e));
    return r;
}

__global__ __launch_bounds__(256) void nca_step(
    const float* __restrict__ img,
    const float* __restrict__ comms_w,
    const float* __restrict__ comms_b,
    const float* __restrict__ perc_w,
    const float* __restrict__ perc_b,
    const float* __restrict__ out_w,
    const float* __restrict__ out_b,
    float* __restrict__ out,
    int parity)
{
    __shared__ __align__(16) float scw[9 * 96];   // comms_w [ij][c]
    __shared__ __align__(16) float su[100], sv[100], sob[100];
    __shared__ float spw[9];
    __shared__ float sbias[2];                    // [0]=perc_b [1]=comms_b

    int t = threadIdx.y * 32 + threadIdx.x;
    for (int i = t; i < 864; i += 256) scw[i] = comms_w[i];
    if (t < 98) { su[t] = out_w[t]; sv[t] = out_w[98 + t]; sob[t] = out_b[t]; }
    else if (t >= 128 && t < 137) spw[t - 128] = perc_w[t - 128];
    else if (t == 137) sbias[0] = perc_b[0];
    else if (t == 138) sbias[1] = comms_b[0];
    __syncthreads();

    int n = blockIdx.y * 8 + threadIdx.y;
    if (n >= N_NEO) return;
    int m0 = blockIdx.x * 128 + threadIdx.x;

    const float* __restrict__ hOld = &g_h[parity][0][0];
    float* __restrict__ hNew = &g_h[parity ^ 1][0][0];

    bool valid[4];
    int  cellc[4];            // clamped cell index (safe reads)
    float a[4], b[4];
    ushort2 pp[4];

#pragma unroll
    for (int u = 0; u < 4; u++) {
        int mm = m0 + 32 * u;
        valid[u] = (mm < N_NEO);
        int mc = mm < N_NEO ? mm : (N_NEO - 1);
        cellc[u] = n * N_NEO + mc;

        // comms gather over 9 planes
        float av = sbias[1];
#pragma unroll
        for (int q = 0; q < 9; q++) {
            int i = q / 3, j = q % 3;
            av += hOld[q * G2 + (n + i) * G + (mc + j)];
        }
        a[u] = av;

        // perception: 3x3 img patch at perc position
        ushort2 p = g_perc[cellc[u]];
        pp[u] = p;
        float bv = sbias[0];
#pragma unroll
        for (int q = 0; q < 9; q++) {
            int i = q / 3, j = q % 3;
            bv = fmaf(img[(p.x + i) * G + (p.y + j)], spw[q], bv);
        }
        b[u] = bv;
    }

    float acc[4][9];
#pragma unroll
    for (int u = 0; u < 4; u++)
#pragma unroll
        for (int q = 0; q < 9; q++) acc[u][q] = 0.0f;

    // ---- hidden channels 0..63 ----
#pragma unroll 4
    for (int c4 = 0; c4 < 64; c4 += 4) {
        float4 u4 = *reinterpret_cast<const float4*>(&su[c4]);
        float4 v4 = *reinterpret_cast<const float4*>(&sv[c4]);
        float4 o4 = *reinterpret_cast<const float4*>(&sob[c4]);
        float s[4][4];
#pragma unroll
        for (int u = 0; u < 4; u++) {
            s[u][0] = sigmoidf(fmaf(a[u], u4.x, fmaf(b[u], v4.x, o4.x)));
            s[u][1] = sigmoidf(fmaf(a[u], u4.y, fmaf(b[u], v4.y, o4.y)));
            s[u][2] = sigmoidf(fmaf(a[u], u4.z, fmaf(b[u], v4.z, o4.z)));
            s[u][3] = sigmoidf(fmaf(a[u], u4.w, fmaf(b[u], v4.w, o4.w)));
        }
#pragma unroll
        for (int q = 0; q < 9; q++) {
            float4 w4 = *reinterpret_cast<const float4*>(&scw[q * 96 + c4]);
#pragma unroll
            for (int u = 0; u < 4; u++)
                acc[u][q] = fmaf(w4.x, s[u][0], fmaf(w4.y, s[u][1],
                            fmaf(w4.z, s[u][2], fmaf(w4.w, s[u][3], acc[u][q]))));
        }
    }

    // ---- class channels 64..95 (also RMW into out) ----
#pragma unroll 2
    for (int c4 = 64; c4 < 96; c4 += 4) {
        float4 u4 = *reinterpret_cast<const float4*>(&su[c4]);
        float4 v4 = *reinterpret_cast<const float4*>(&sv[c4]);
        float4 o4 = *reinterpret_cast<const float4*>(&sob[c4]);
        float s[4][4];
#pragma unroll
        for (int u = 0; u < 4; u++) {
            s[u][0] = sigmoidf(fmaf(a[u], u4.x, fmaf(b[u], v4.x, o4.x)));
            s[u][1] = sigmoidf(fmaf(a[u], u4.y, fmaf(b[u], v4.y, o4.y)));
            s[u][2] = sigmoidf(fmaf(a[u], u4.z, fmaf(b[u], v4.z, o4.z)));
            s[u][3] = sigmoidf(fmaf(a[u], u4.w, fmaf(b[u], v4.w, o4.w)));
        }
#pragma unroll
        for (int u = 0; u < 4; u++) {
            if (valid[u]) {
                float* op = out + (size_t)cellc[u] * 32 + (c4 - 64);
                float4 v = *reinterpret_cast<float4*>(op);
                v.x += s[u][0]; v.y += s[u][1]; v.z += s[u][2]; v.w += s[u][3];
                *reinterpret_cast<float4*>(op) = v;
            }
        }
#pragma unroll
        for (int q = 0; q < 9; q++) {
            float4 w4 = *reinterpret_cast<const float4*>(&scw[q * 96 + c4]);
#pragma unroll
            for (int u = 0; u < 4; u++)
                acc[u][q] = fmaf(w4.x, s[u][0], fmaf(w4.y, s[u][1],
                            fmaf(w4.z, s[u][2], fmaf(w4.w, s[u][3], acc[u][q]))));
        }
    }

    // ---- plane writes + action/perc update ----
    float u96 = su[96], v96 = sv[96], o96 = sob[96];
    float u97 = su[97], v97 = sv[97], o97 = sob[97];
#pragma unroll
    for (int u = 0; u < 4; u++) {
        if (!valid[u]) continue;
        int mm = m0 + 32 * u;
        int hc = (n + 1) * G + (mm + 1);
#pragma unroll
        for (int q = 0; q < 9; q++)
            hNew[q * G2 + hc] = hOld[q * G2 + hc] + acc[u][q];

        float s0 = sigmoidf(fmaf(a[u], u96, fmaf(b[u], v96, o96)));
        float s1 = sigmoidf(fmaf(a[u], u97, fmaf(b[u], v97, o97)));
        int dx = (s0 > NCA_THRESH) ? 1 : ((s0 < -NCA_THRESH) ? -1 : 0);
        int dy = (s1 > NCA_THRESH) ? 1 : ((s1 < -NCA_THRESH) ? -1 : 0);
        int px = min(max((int)pp[u].x + dx, 0), N_NEO - 1);
        int py = min(max((int)pp[u].y + dy, 0), N_NEO - 1);
        g_perc[cellc[u]] = make_ushort2((unsigned short)px, (unsigned short)py);
    }
}

extern "C" void kernel_launch(void* const* d_in, const int* in_sizes, int n_in,
                              void* d_out, int out_size) {
    const float* img     = (const float*)d_in[0];
    const float* comms_w = (const float*)d_in[1];
    const float* comms_b = (const float*)d_in[2];
    const float* perc_w  = (const float*)d_in[3];
    const float* perc_b  = (const float*)d_in[4];
    const float* out_w   = (const float*)d_in[5];
    const float* out_b   = (const float*)d_in[6];
    float* out = (float*)d_out;

    nca_init<<<1024, 256>>>(out);

    dim3 bs(32, 8);
    dim3 gs((N_NEO + 127) / 128, (N_NEO + 7) / 8);
    for (int t = 0; t < 50; t++)
        nca_step<<<gs, bs>>>(img, comms_w, comms_b, perc_w, perc_b,
                             out_w, out_b, out, t & 1);
}

// round 3
// speedup vs baseline: 1.9065x; 1.1429x over previous
#include <cuda_runtime.h>

// MovingNCA, plane-reduced formulation:
//  state(96ch) replaced by 9 planes P_ij = <state, comms_w[i,j,:]>.
//  comms a = b_c + sum_ij P_ij(n+i,m+j); percep b = 3x3 img gather at perc pos.
//  s_c = sigmoid(a*u_c + b*v_c + ob_c); planes += W^T s; class ch -> scratch.
// R3: 128-thread blocks (512 blocks, ~1 balanced wave) + transposed class
//     scratch g_cls[k][cell] (coalesced RMW; kills the 32-wf/instr out RMW),
//     final transpose kernel produces out[cell][32].

#define N_NEO 510
#define G     512
#define G2    (G * G)
#define NCELLS (N_NEO * N_NEO)
#define NCA_THRESH 0.0007f

__device__ float   g_h[2][9][G2];       // ping-pong comms planes
__device__ float   g_cls[32][NCELLS];   // transposed class accumulators
__device__ ushort2 g_perc[NCELLS];      // perception positions

__global__ void nca_init() {
    long stride = (long)gridDim.x * blockDim.x;
    long tid = (long)blockIdx.x * blockDim.x + threadIdx.x;
    float* h = &g_h[0][0][0];
    for (long i = tid; i < 2L * 9 * G2; i += stride) h[i] = 0.0f;
    float* c = &g_cls[0][0];
    for (long i = tid; i < 32L * NCELLS; i += stride) c[i] = 0.0f;
    for (long i = tid; i < NCELLS; i += stride)
        g_perc[i] = make_ushort2((unsigned short)(i / N_NEO),
                                 (unsigned short)(i % N_NEO));
}

__global__ void nca_final(float* __restrict__ out) {
    int cell = blockIdx.x * 256 + threadIdx.x;
    if (cell >= NCELLS) return;
    float* op = out + (size_t)cell * 32;
#pragma unroll
    for (int k = 0; k < 32; k += 4) {
        float4 v;
        v.x = g_cls[k + 0][cell];
        v.y = g_cls[k + 1][cell];
        v.z = g_cls[k + 2][cell];
        v.w = g_cls[k + 3][cell];
        *reinterpret_cast<float4*>(op + k) = v;
    }
}

__device__ __forceinline__ float sigmoidf(float x) {
    float e;
    asm("ex2.approx.f32 %0, %1;" : "=f"(e) : "f"(-1.442695041f * x));
    float r;
    asm("rcp.approx.f32 %0, %1;" : "=f"(r) : "f"(1.0f + e));
    return r;
}

__global__ __launch_bounds__(128, 4) void nca_step(
    const float* __restrict__ img,
    const float* __restrict__ comms_w,
    const float* __restrict__ comms_b,
    const float* __restrict__ perc_w,
    const float* __restrict__ perc_b,
    const float* __restrict__ out_w,
    const float* __restrict__ out_b,
    int parity)
{
    __shared__ __align__(16) float scw[9 * 96];   // comms_w [ij][c]
    __shared__ __align__(16) float su[100], sv[100], sob[100];
    __shared__ float spw[9];
    __shared__ float sbias[2];                    // [0]=perc_b [1]=comms_b

    int t = threadIdx.y * 32 + threadIdx.x;
    for (int i = t; i < 864; i += 128) scw[i] = comms_w[i];
    if (t < 98) { su[t] = out_w[t]; sv[t] = out_w[98 + t]; sob[t] = out_b[t]; }
    else if (t >= 98 && t < 107) spw[t - 98] = perc_w[t - 98];
    else if (t == 107) sbias[0] = perc_b[0];
    else if (t == 108) sbias[1] = comms_b[0];
    __syncthreads();

    int n = blockIdx.y * 4 + threadIdx.y;
    if (n >= N_NEO) return;
    int m0 = blockIdx.x * 128 + threadIdx.x;

    const float* __restrict__ hOld = &g_h[parity][0][0];
    float* __restrict__ hNew = &g_h[parity ^ 1][0][0];

    bool valid[4];
    int  cellc[4];            // clamped cell index (safe reads)
    float a[4], b[4];
    ushort2 pp[4];

#pragma unroll
    for (int u = 0; u < 4; u++) {
        int mm = m0 + 32 * u;
        valid[u] = (mm < N_NEO);
        int mc = mm < N_NEO ? mm : (N_NEO - 1);
        cellc[u] = n * N_NEO + mc;

        // comms gather over 9 planes
        float av = sbias[1];
#pragma unroll
        for (int q = 0; q < 9; q++) {
            int i = q / 3, j = q % 3;
            av += hOld[q * G2 + (n + i) * G + (mc + j)];
        }
        a[u] = av;

        // perception: 3x3 img patch at perc position
        ushort2 p = g_perc[cellc[u]];
        pp[u] = p;
        float bv = sbias[0];
#pragma unroll
        for (int q = 0; q < 9; q++) {
            int i = q / 3, j = q % 3;
            bv = fmaf(img[(p.x + i) * G + (p.y + j)], spw[q], bv);
        }
        b[u] = bv;
    }

    float acc[4][9];
#pragma unroll
    for (int u = 0; u < 4; u++)
#pragma unroll
        for (int q = 0; q < 9; q++) acc[u][q] = 0.0f;

    // ---- hidden channels 0..63 ----
#pragma unroll 4
    for (int c4 = 0; c4 < 64; c4 += 4) {
        float4 u4 = *reinterpret_cast<const float4*>(&su[c4]);
        float4 v4 = *reinterpret_cast<const float4*>(&sv[c4]);
        float4 o4 = *reinterpret_cast<const float4*>(&sob[c4]);
        float s[4][4];
#pragma unroll
        for (int u = 0; u < 4; u++) {
            s[u][0] = sigmoidf(fmaf(a[u], u4.x, fmaf(b[u], v4.x, o4.x)));
            s[u][1] = sigmoidf(fmaf(a[u], u4.y, fmaf(b[u], v4.y, o4.y)));
            s[u][2] = sigmoidf(fmaf(a[u], u4.z, fmaf(b[u], v4.z, o4.z)));
            s[u][3] = sigmoidf(fmaf(a[u], u4.w, fmaf(b[u], v4.w, o4.w)));
        }
#pragma unroll
        for (int q = 0; q < 9; q++) {
            float4 w4 = *reinterpret_cast<const float4*>(&scw[q * 96 + c4]);
#pragma unroll
            for (int u = 0; u < 4; u++)
                acc[u][q] = fmaf(w4.x, s[u][0], fmaf(w4.y, s[u][1],
                            fmaf(w4.z, s[u][2], fmaf(w4.w, s[u][3], acc[u][q]))));
        }
    }

    // ---- class channels 64..95 (also RMW into transposed scratch) ----
#pragma unroll 2
    for (int c4 = 64; c4 < 96; c4 += 4) {
        float4 u4 = *reinterpret_cast<const float4*>(&su[c4]);
        float4 v4 = *reinterpret_cast<const float4*>(&sv[c4]);
        float4 o4 = *reinterpret_cast<const float4*>(&sob[c4]);
        float s[4][4];
#pragma unroll
        for (int u = 0; u < 4; u++) {
            s[u][0] = sigmoidf(fmaf(a[u], u4.x, fmaf(b[u], v4.x, o4.x)));
            s[u][1] = sigmoidf(fmaf(a[u], u4.y, fmaf(b[u], v4.y, o4.y)));
            s[u][2] = sigmoidf(fmaf(a[u], u4.z, fmaf(b[u], v4.z, o4.z)));
            s[u][3] = sigmoidf(fmaf(a[u], u4.w, fmaf(b[u], v4.w, o4.w)));
        }
#pragma unroll
        for (int u = 0; u < 4; u++) {
            if (valid[u]) {
                int cc = cellc[u];
#pragma unroll
                for (int k = 0; k < 4; k++)
                    g_cls[c4 - 64 + k][cc] += s[u][k];   // coalesced across lanes
            }
        }
#pragma unroll
        for (int q = 0; q < 9; q++) {
            float4 w4 = *reinterpret_cast<const float4*>(&scw[q * 96 + c4]);
#pragma unroll
            for (int u = 0; u < 4; u++)
                acc[u][q] = fmaf(w4.x, s[u][0], fmaf(w4.y, s[u][1],
                            fmaf(w4.z, s[u][2], fmaf(w4.w, s[u][3], acc[u][q]))));
        }
    }

    // ---- plane writes + action/perc update ----
    float u96 = su[96], v96 = sv[96], o96 = sob[96];
    float u97 = su[97], v97 = sv[97], o97 = sob[97];
#pragma unroll
    for (int u = 0; u < 4; u++) {
        if (!valid[u]) continue;
        int mm = m0 + 32 * u;
        int hc = (n + 1) * G + (mm + 1);
#pragma unroll
        for (int q = 0; q < 9; q++)
            hNew[q * G2 + hc] = hOld[q * G2 + hc] + acc[u][q];

        float s0 = sigmoidf(fmaf(a[u], u96, fmaf(b[u], v96, o96)));
        float s1 = sigmoidf(fmaf(a[u], u97, fmaf(b[u], v97, o97)));
        int dx = (s0 > NCA_THRESH) ? 1 : ((s0 < -NCA_THRESH) ? -1 : 0);
        int dy = (s1 > NCA_THRESH) ? 1 : ((s1 < -NCA_THRESH) ? -1 : 0);
        int px = min(max((int)pp[u].x + dx, 0), N_NEO - 1);
        int py = min(max((int)pp[u].y + dy, 0), N_NEO - 1);
        g_perc[cellc[u]] = make_ushort2((unsigned short)px, (unsigned short)py);
    }
}

extern "C" void kernel_launch(void* const* d_in, const int* in_sizes, int n_in,
                              void* d_out, int out_size) {
    const float* img     = (const float*)d_in[0];
    const float* comms_w = (const float*)d_in[1];
    const float* comms_b = (const float*)d_in[2];
    const float* perc_w  = (const float*)d_in[3];
    const float* perc_b  = (const float*)d_in[4];
    const float* out_w   = (const float*)d_in[5];
    const float* out_b   = (const float*)d_in[6];
    float* out = (float*)d_out;

    nca_init<<<1024, 256>>>();

    dim3 bs(32, 4);
    dim3 gs((N_NEO + 127) / 128, (N_NEO + 3) / 4);
    for (int t = 0; t < 50; t++)
        nca_step<<<gs, bs>>>(img, comms_w, comms_b, perc_w, perc_b,
                             out_w, out_b, t & 1);

    nca_final<<<(NCELLS + 255) / 256, 256>>>(out);
}